// round 16
// baseline (speedup 1.0000x reference)
#include <cuda_runtime.h>
#include <cuda_fp16.h>
#include <cstdint>

// Problem constants (fixed by the dataset)
#define NN    50000
#define EE    800000
#define INDIM 64
#define HID   256
#define OUTD  128
#define C2    512   // 2*HID

// ---------------- device scratch (static: no allocation allowed) ----------------
__device__ __half g_x16 [NN * INDIM];   // x (fp16)
__device__ __half g_xa16[NN * INDIM];   // A_norm x (fp16)
__device__ __half g_x3f [NN * C2];      // x3 (fp16)
__device__ __half g_b1h[C2 * INDIM];    // B1[n][k] = concat(w_fc,w_conv1)^T fp16 hi
__device__ __half g_b1l[C2 * INDIM];    //                                  fp16 lo
__device__ __half g_b2h[256 * C2];      // B2[n][k] = concat(w_fc1,w_conv2)^T fp16 (hi only)
__device__ __half g_xc2[NN * OUTD];  // x3 @ w_conv2 (raw, fp16 — gather-bandwidth critical)
__device__ float g_x7 [NN * OUTD];   // x5 (fc1 branch)
__device__ float g_xc3[NN];
__device__ float g_pre[NN];
__device__ float g_dis[NN];
__device__ int   g_deg[NN];
__device__ int   g_colptr[NN + 1];
__device__ int   g_cursor[NN];
__device__ int   g_erow[EE];
__device__ float g_ewt [EE];
__device__ int   g_bsum[1024];
__device__ int   g_is64;

// ---------------- mma.sync helpers (sm_80-era PTX: valid on plain sm_103) ----------------
__device__ __forceinline__ uint32_t smem_u32(const void* p) {
    uint32_t a;
    asm("{ .reg .u64 t; cvta.to.shared.u64 t, %1; cvt.u32.u64 %0, t; }" : "=r"(a) : "l"(p));
    return a;
}
__device__ __forceinline__ void ldsm4(uint32_t* d, uint32_t addr) {
    asm volatile("ldmatrix.sync.aligned.m8n8.x4.shared.b16 {%0,%1,%2,%3}, [%4];"
                 : "=r"(d[0]), "=r"(d[1]), "=r"(d[2]), "=r"(d[3]) : "r"(addr));
}
__device__ __forceinline__ void mma_f16(float* c, const uint32_t* a, uint32_t b0, uint32_t b1) {
    asm volatile(
        "mma.sync.aligned.m16n8k16.row.col.f32.f16.f16.f32 "
        "{%0,%1,%2,%3}, {%4,%5,%6,%7}, {%8,%9}, {%0,%1,%2,%3};"
        : "+f"(c[0]), "+f"(c[1]), "+f"(c[2]), "+f"(c[3])
        : "r"(a[0]), "r"(a[1]), "r"(a[2]), "r"(a[3]), "r"(b0), "r"(b1));
}
__device__ __forceinline__ void fsplit16(float v, __half& h, __half& l) {
    h = __float2half(v);
    l = __float2half(v - __half2float(h));
}
// cp.async 16B with zero-fill predicate (src-size 0 -> zeros)
__device__ __forceinline__ void cpa(uint32_t dst, const void* src, int pred) {
    asm volatile("cp.async.cg.shared.global [%0], [%1], 16, %2;"
                 :: "r"(dst), "l"(src), "r"(pred ? 16 : 0) : "memory");
}
#define CP_COMMIT() asm volatile("cp.async.commit_group;" ::: "memory")
#define CP_WAIT(N)  asm volatile("cp.async.wait_group %0;" :: "n"(N) : "memory")

// SMEM layout GEMM1: 128 rows x 64 fp16, stride 72 elems (144B rows, conflict-free ldmatrix)
#define LDS    72
#define TILEB  (128 * LDS * 2)     // 18432 bytes
#define G_A    0
#define G_BH   TILEB
#define G_BL   (2 * TILEB)
#define G1_SMEM (3 * TILEB)        // 55296

// SMEM layout GEMM2 (N-merged, hi-only B): A 128x64 + B 256x64 per stage
#define G2S_A   0
#define G2S_BH  TILEB              // 18432
#define G2_STAGE (3 * TILEB)       // 55296
#define G2_SMEM (2 * G2_STAGE)     // 110592 (double buffered)

// One K=64 chunk: 2-product fp16 GEMM (A single, B hi/lo). MF = #m-frags per warp. (gemm1)
template <int MF>
__device__ __forceinline__ void chunk64(uint32_t base, uint32_t offA, uint32_t offB,
                                        float acc[][4][4]) {
    #pragma unroll
    for (int ks = 0; ks < 4; ks++) {
        uint32_t ka = ks * 32;                      // k16 step = 16 fp16 = 32 bytes
        uint32_t a[MF][4], bh[4][2], bl[4][2];
        #pragma unroll
        for (int mi = 0; mi < MF; mi++) ldsm4(a[mi], base + G_A + offA + mi * 2304 + ka);
        #pragma unroll
        for (int nj = 0; nj < 2; nj++) {
            uint32_t t[4];
            ldsm4(t, base + G_BH + offB + nj * 2304 + ka);
            bh[nj * 2][0] = t[0]; bh[nj * 2][1] = t[1];
            bh[nj * 2 + 1][0] = t[2]; bh[nj * 2 + 1][1] = t[3];
            ldsm4(t, base + G_BL + offB + nj * 2304 + ka);
            bl[nj * 2][0] = t[0]; bl[nj * 2][1] = t[1];
            bl[nj * 2 + 1][0] = t[2]; bl[nj * 2 + 1][1] = t[3];
        }
        #pragma unroll
        for (int mi = 0; mi < MF; mi++)
            #pragma unroll
            for (int nf = 0; nf < 4; nf++) {
                mma_f16(acc[mi][nf], a[mi], bh[nf][0], bh[nf][1]);
                mma_f16(acc[mi][nf], a[mi], bl[nf][0], bl[nf][1]);
            }
    }
}

// gemm2 chunk: MF=2, NF=8, single B product (hi only): 6 LDSM feed 16 MMA per k-step.
__device__ __forceinline__ void chunk64_g2(uint32_t base, uint32_t offA, uint32_t offB,
                                           float acc[2][8][4]) {
    #pragma unroll
    for (int ks = 0; ks < 4; ks++) {
        uint32_t ka = ks * 32;
        uint32_t a[2][4], bh[8][2];
        #pragma unroll
        for (int mi = 0; mi < 2; mi++) ldsm4(a[mi], base + G2S_A + offA + mi * 2304 + ka);
        #pragma unroll
        for (int nj = 0; nj < 4; nj++) {
            uint32_t t[4];
            ldsm4(t, base + G2S_BH + offB + nj * 2304 + ka);
            bh[nj * 2][0] = t[0]; bh[nj * 2][1] = t[1];
            bh[nj * 2 + 1][0] = t[2]; bh[nj * 2 + 1][1] = t[3];
        }
        #pragma unroll
        for (int mi = 0; mi < 2; mi++)
            #pragma unroll
            for (int nf = 0; nf < 8; nf++)
                mma_f16(acc[mi][nf], a[mi], bh[nf][0], bh[nf][1]);
    }
}

// ---------------- edge dtype handling ----------------
__global__ void detect_kernel(const int* __restrict__ p, int nwords) {
    __shared__ int any;
    if (threadIdx.x == 0) any = 0;
    __syncthreads();
    int v = 0;
    for (int i = threadIdx.x; i < nwords; i += blockDim.x)
        if (i & 1) v |= p[i];
    if (v) atomicOr(&any, 1);
    __syncthreads();
    if (threadIdx.x == 0) g_is64 = (any == 0) ? 1 : 0;
}
__device__ __forceinline__ int edge_val(const void* e, long idx) {
    if (g_is64) return (int)((const long long*)e)[idx];
    return ((const int*)e)[idx];
}

// ---------------- CSR build ----------------
__global__ void zero_deg_kernel(int n) {
    int i = blockIdx.x * blockDim.x + threadIdx.x;
    if (i < n) g_deg[i] = 0;
}
__global__ void count_kernel(const void* __restrict__ edges, int E) {
    int e = blockIdx.x * blockDim.x + threadIdx.x;
    if (e < E) atomicAdd(&g_deg[edge_val(edges, (long)E + e)], 1);
}
#define SCB 512
__global__ void scan_blocks_kernel(int n) {
    __shared__ int sm[SCB];
    int i = blockIdx.x * SCB + threadIdx.x;
    int v = (i < n) ? g_deg[i] : 0;
    sm[threadIdx.x] = v;
    __syncthreads();
    for (int off = 1; off < SCB; off <<= 1) {
        int t = 0;
        if ((int)threadIdx.x >= off) t = sm[threadIdx.x - off];
        __syncthreads();
        sm[threadIdx.x] += t;
        __syncthreads();
    }
    if (i < n) g_colptr[i] = sm[threadIdx.x] - v;
    if (threadIdx.x == SCB - 1) g_bsum[blockIdx.x] = sm[SCB - 1];
}
__global__ void scan_sums_kernel(int nb) {
    __shared__ int sm[1024];
    int v = (threadIdx.x < (unsigned)nb) ? g_bsum[threadIdx.x] : 0;
    sm[threadIdx.x] = v;
    __syncthreads();
    for (int off = 1; off < 1024; off <<= 1) {
        int t = 0;
        if ((int)threadIdx.x >= off) t = sm[threadIdx.x - off];
        __syncthreads();
        sm[threadIdx.x] += t;
        __syncthreads();
    }
    if (threadIdx.x < (unsigned)nb) g_bsum[threadIdx.x] = sm[threadIdx.x] - v;
}
__global__ void scan_add_kernel(int n, int Etot) {
    int i = blockIdx.x * SCB + threadIdx.x;
    if (i < n) {
        int v = g_colptr[i] + g_bsum[blockIdx.x];
        g_colptr[i] = v;
        g_cursor[i] = v;
        int d = g_deg[i];
        g_dis[i] = (d > 0) ? rsqrtf((float)d) : 0.0f;
    }
    if (i == 0) g_colptr[n] = Etot;
}
__global__ void fill_kernel(const void* __restrict__ edges, int E) {
    int e = blockIdx.x * blockDim.x + threadIdx.x;
    if (e < E) {
        int r = edge_val(edges, e);
        int c = edge_val(edges, (long)E + e);
        int pos = atomicAdd(&g_cursor[c], 1);
        g_erow[pos] = r;
        g_ewt[pos]  = g_dis[r];
    }
}

// ---------------- conversions ----------------
__global__ void conv_x_kernel(const float* __restrict__ x, int total) {
    int i = blockIdx.x * blockDim.x + threadIdx.x;
    if (i < total) g_x16[i] = __float2half(x[i]);
}
// B1[n][k] = (n<256 ? w_fc[k][n] : w_conv1[k][n-256]),  [512 x 64], fp16 hi/lo
__global__ void conv_w1_kernel(const float* __restrict__ w_fc, const float* __restrict__ w_conv1) {
    int i = blockIdx.x * blockDim.x + threadIdx.x;   // 512*64
    int nidx = i >> 6, k = i & 63;
    float v = (nidx < 256) ? w_fc[k * 256 + nidx] : w_conv1[k * 256 + (nidx - 256)];
    fsplit16(v, g_b1h[i], g_b1l[i]);
}
// B2[n][k] = (n<128 ? w_fc1[k][n] : w_conv2[k][n-128]),  [256 x 512], fp16 (hi only)
__global__ void conv_w2_kernel(const float* __restrict__ w_fc1, const float* __restrict__ w_conv2) {
    int i = blockIdx.x * blockDim.x + threadIdx.x;   // 256*512
    int nidx = i >> 9, k = i & 511;
    float v = (nidx < 128) ? w_fc1[k * 128 + nidx] : w_conv2[k * 128 + (nidx - 128)];
    g_b2h[i] = __float2half(v);
}

// ---------------- Aggregate X (propagate-then-transform for conv1) ----------------
// Gathers from fp16 x (half the traffic), accumulates fp32, 2-way unrolled.
__global__ __launch_bounds__(128) void aggx_kernel(int n) {
    int node = blockIdx.x * 8 + (threadIdx.x >> 4);
    int f4 = threadIdx.x & 15;
    if (node >= n) return;
    int s = g_colptr[node], e = g_colptr[node + 1];
    float4 acc = make_float4(0.f, 0.f, 0.f, 0.f);
    float4 acc2 = make_float4(0.f, 0.f, 0.f, 0.f);
    int p = s;
    for (; p + 2 <= e; p += 2) {
        int r0 = g_erow[p], r1 = g_erow[p + 1];
        float w0 = g_ewt[p], w1 = g_ewt[p + 1];
        uint2 u0 = ((const uint2*)g_x16)[(long)r0 * 16 + f4];
        uint2 u1 = ((const uint2*)g_x16)[(long)r1 * 16 + f4];
        float2 a0 = __half22float2(*(__half2*)&u0.x), b0 = __half22float2(*(__half2*)&u0.y);
        float2 a1 = __half22float2(*(__half2*)&u1.x), b1 = __half22float2(*(__half2*)&u1.y);
        acc.x += w0 * a0.x; acc.y += w0 * a0.y; acc.z += w0 * b0.x; acc.w += w0 * b0.y;
        acc2.x += w1 * a1.x; acc2.y += w1 * a1.y; acc2.z += w1 * b1.x; acc2.w += w1 * b1.y;
    }
    if (p < e) {
        int r0 = g_erow[p];
        float w0 = g_ewt[p];
        uint2 u0 = ((const uint2*)g_x16)[(long)r0 * 16 + f4];
        float2 a0 = __half22float2(*(__half2*)&u0.x), b0 = __half22float2(*(__half2*)&u0.y);
        acc.x += w0 * a0.x; acc.y += w0 * a0.y; acc.z += w0 * b0.x; acc.w += w0 * b0.y;
    }
    acc.x += acc2.x; acc.y += acc2.y; acc.z += acc2.z; acc.w += acc2.w;
    float di = g_dis[node];
    __half2 h01, h23;
    h01.x = __float2half(acc.x * di); h01.y = __float2half(acc.y * di);
    h23.x = __float2half(acc.z * di); h23.y = __float2half(acc.w * di);
    long base = (long)node * 64 + f4 * 4;
    *(__half2*)(g_xa16 + base)     = h01;
    *(__half2*)(g_xa16 + base + 2) = h23;
}

// ================= GEMM1 (HMMA fp16): [N,64] @ [64,512] -> x3 fp16 (relu+bias) ========
// ybase+y in {0,1}: A = x16,  bias b_fc     -> x1 (cols 0..255)
// ybase+y in {2,3}: A = xa16, bias b_conv1  -> x2 (cols 256..511)
__global__ __launch_bounds__(256) void gemm1_mma(const float* __restrict__ b_fc,
                                                 const float* __restrict__ b_conv1,
                                                 int ybase, int n) {
    extern __shared__ char smem[];
    uint32_t sb = smem_u32(smem);
    int tid = threadIdx.x, wid = tid >> 5, lane = tid & 31;
    int bm0 = blockIdx.x * 128, bn0 = (blockIdx.y + ybase) * 128;
    bool isfc = bn0 < 256;
    const __half* A = isfc ? g_x16 : g_xa16;
    int wm = (wid >> 2) * 64, wn = (wid & 3) * 32;

    #pragma unroll
    for (int i = 0; i < 4; i++) {
        int t = tid + i * 256;
        int row = t >> 3, j = t & 7;
        long grow = bm0 + row;
        uint4 va = make_uint4(0u, 0u, 0u, 0u);
        if (grow < n) va = ((const uint4*)(A + grow * 64))[j];
        *(uint4*)(smem + G_A + row * 144 + j * 16) = va;
        long rb = bn0 + row;
        *(uint4*)(smem + G_BH + row * 144 + j * 16) = ((const uint4*)(g_b1h + rb * 64))[j];
        *(uint4*)(smem + G_BL + row * 144 + j * 16) = ((const uint4*)(g_b1l + rb * 64))[j];
    }
    __syncthreads();

    int g = lane >> 3, r = lane & 7;
    uint32_t offA = (uint32_t)(((wm + (g & 1) * 8 + r) * LDS + (g >> 1) * 8) * 2);
    uint32_t offB = (uint32_t)(((wn + (g >> 1) * 8 + r) * LDS + (g & 1) * 8) * 2);

    float acc[4][4][4];
    #pragma unroll
    for (int mi = 0; mi < 4; mi++)
        #pragma unroll
        for (int nf = 0; nf < 4; nf++)
            #pragma unroll
            for (int q = 0; q < 4; q++) acc[mi][nf][q] = 0.f;

    chunk64<4>(sb, offA, offB, acc);

    int qrow = lane >> 2, qcol = (lane & 3) * 2;
    #pragma unroll
    for (int mi = 0; mi < 4; mi++) {
        int r0 = bm0 + wm + mi * 16 + qrow;
        int r1 = r0 + 8;
        #pragma unroll
        for (int nf = 0; nf < 4; nf++) {
            int col = bn0 + wn + nf * 8 + qcol;
            float* c = acc[mi][nf];
            float2 bb = isfc ? *(const float2*)(b_fc + col)
                             : *(const float2*)(b_conv1 + (col - 256));
            if (r0 < n) {
                __half2 o;
                o.x = __float2half(fmaxf(c[0] + bb.x, 0.f));
                o.y = __float2half(fmaxf(c[1] + bb.y, 0.f));
                *(__half2*)(g_x3f + (long)r0 * C2 + col) = o;
            }
            if (r1 < n) {
                __half2 o;
                o.x = __float2half(fmaxf(c[2] + bb.x, 0.f));
                o.y = __float2half(fmaxf(c[3] + bb.y, 0.f));
                *(__half2*)(g_x3f + (long)r1 * C2 + col) = o;
            }
        }
    }
}

// ================= GEMM2 (HMMA fp16, N-merged 128x256 tile, hi-only B, cp.async 2-stage) ====
// cols 0..127  -> relu(+b_fc1) -> g_x7 (x5, fp32)
// cols 128..255-> raw fp16     -> g_xc2
__global__ __launch_bounds__(512) void gemm2_mma(const float* __restrict__ b_fc1, int n) {
    extern __shared__ char smem[];
    uint32_t sb = smem_u32(smem);
    int tid = threadIdx.x, wid = tid >> 5, lane = tid & 31;
    int bm0 = blockIdx.x * 128;
    int wm = (wid & 3) * 32, wn = (wid >> 2) * 64;   // 16 warps: 4 m x 4 n of 32x64
    bool isfc = wn < 128;

    auto issue = [&](int c, int buf) {
        uint32_t base = sb + buf * G2_STAGE;
        int k0 = c * 64;
        // A: 1024 quads
        #pragma unroll
        for (int i = 0; i < 2; i++) {
            int t = tid + i * 512;
            int row = t >> 3, j = t & 7;
            long grow = bm0 + row;
            int pred = grow < n;
            cpa(base + G2S_A + row * 144 + j * 16,
                g_x3f + (pred ? grow : 0) * C2 + k0 + j * 8, pred);
        }
        // B hi: 2048 quads (rows 0..255 global)
        #pragma unroll
        for (int i = 0; i < 4; i++) {
            int t = tid + i * 512;
            int row = t >> 3, j = t & 7;
            cpa(base + G2S_BH + row * 144 + j * 16, g_b2h + (long)row * C2 + k0 + j * 8, 1);
        }
        CP_COMMIT();
    };

    int g = lane >> 3, r = lane & 7;
    uint32_t offA = (uint32_t)(((wm + (g & 1) * 8 + r) * LDS + (g >> 1) * 8) * 2);
    uint32_t offB = (uint32_t)(((wn + (g >> 1) * 8 + r) * LDS + (g & 1) * 8) * 2);

    float acc[2][8][4];
    #pragma unroll
    for (int mi = 0; mi < 2; mi++)
        #pragma unroll
        for (int nf = 0; nf < 8; nf++)
            #pragma unroll
            for (int q = 0; q < 4; q++) acc[mi][nf][q] = 0.f;

    issue(0, 0);
    for (int c = 0; c < 8; c++) {
        if (c < 7) {
            issue(c + 1, (c + 1) & 1);
            CP_WAIT(1);
        } else {
            CP_WAIT(0);
        }
        __syncthreads();
        chunk64_g2(sb + (c & 1) * G2_STAGE, offA, offB, acc);
        __syncthreads();
    }

    int qrow = lane >> 2, qcol = (lane & 3) * 2;
    #pragma unroll
    for (int mi = 0; mi < 2; mi++) {
        int r0 = bm0 + wm + mi * 16 + qrow;
        int r1 = r0 + 8;
        #pragma unroll
        for (int nf = 0; nf < 8; nf++) {
            int col = wn + nf * 8 + qcol;     // 0..255
            float* c = acc[mi][nf];
            if (isfc) {
                float2 bb = *(const float2*)(b_fc1 + col);
                if (r0 < n) {
                    float2 o = make_float2(fmaxf(c[0] + bb.x, 0.f), fmaxf(c[1] + bb.y, 0.f));
                    *(float2*)(g_x7 + (long)r0 * OUTD + col) = o;
                }
                if (r1 < n) {
                    float2 o = make_float2(fmaxf(c[2] + bb.x, 0.f), fmaxf(c[3] + bb.y, 0.f));
                    *(float2*)(g_x7 + (long)r1 * OUTD + col) = o;
                }
            } else {
                int cc = col - 128;
                if (r0 < n) {
                    __half2 o; o.x = __float2half(c[0]); o.y = __float2half(c[1]);
                    *(__half2*)(g_xc2 + (long)r0 * OUTD + cc) = o;
                }
                if (r1 < n) {
                    __half2 o; o.x = __float2half(c[2]); o.y = __float2half(c[3]);
                    *(__half2*)(g_xc2 + (long)r1 * OUTD + cc) = o;
                }
            }
        }
    }
}

// ---------- Fused aggregate conv2 + head (fp16 gather, 2-way unrolled) ----------
__global__ __launch_bounds__(128) void agg2_head_kernel(
    const float* __restrict__ b_conv2, const float* __restrict__ w_fc2,
    const float* __restrict__ b_fc2, const float* __restrict__ w_conv3, int n)
{
    int node = blockIdx.x * 4 + (threadIdx.x >> 5);
    int f4 = threadIdx.x & 31;
    if (node >= n) return;
    int s = g_colptr[node], e = g_colptr[node + 1];
    float4 acc = make_float4(0.f, 0.f, 0.f, 0.f);
    float4 acc2 = make_float4(0.f, 0.f, 0.f, 0.f);
    int p = s;
    for (; p + 2 <= e; p += 2) {
        int r0 = g_erow[p], r1 = g_erow[p + 1];
        float w0 = g_ewt[p], w1 = g_ewt[p + 1];
        uint2 u0 = ((const uint2*)g_xc2)[(long)r0 * 32 + f4];
        uint2 u1 = ((const uint2*)g_xc2)[(long)r1 * 32 + f4];
        float2 a0 = __half22float2(*(__half2*)&u0.x), b0 = __half22float2(*(__half2*)&u0.y);
        float2 a1 = __half22float2(*(__half2*)&u1.x), b1 = __half22float2(*(__half2*)&u1.y);
        acc.x += w0 * a0.x; acc.y += w0 * a0.y; acc.z += w0 * b0.x; acc.w += w0 * b0.y;
        acc2.x += w1 * a1.x; acc2.y += w1 * a1.y; acc2.z += w1 * b1.x; acc2.w += w1 * b1.y;
    }
    if (p < e) {
        int r0 = g_erow[p];
        float w0 = g_ewt[p];
        uint2 u0 = ((const uint2*)g_xc2)[(long)r0 * 32 + f4];
        float2 a0 = __half22float2(*(__half2*)&u0.x), b0 = __half22float2(*(__half2*)&u0.y);
        acc.x += w0 * a0.x; acc.y += w0 * a0.y; acc.z += w0 * b0.x; acc.w += w0 * b0.y;
    }
    acc.x += acc2.x; acc.y += acc2.y; acc.z += acc2.z; acc.w += acc2.w;
    float di = g_dis[node];
    float4 b = ((const float4*)b_conv2)[f4];
    float4 cur = ((const float4*)g_x7)[(long)node * 32 + f4];   // x5
    cur.x += fmaxf(acc.x * di + b.x, 0.f);
    cur.y += fmaxf(acc.y * di + b.y, 0.f);
    cur.z += fmaxf(acc.z * di + b.z, 0.f);
    cur.w += fmaxf(acc.w * di + b.w, 0.f);
    // head dots (x7 never stored)
    float4 wf = ((const float4*)w_fc2)[f4];
    float4 wc = ((const float4*)w_conv3)[f4];
    float d1 = cur.x * wf.x + cur.y * wf.y + cur.z * wf.z + cur.w * wf.w;
    float d2 = cur.x * wc.x + cur.y * wc.y + cur.z * wc.z + cur.w * wc.w;
    #pragma unroll
    for (int off = 16; off > 0; off >>= 1) {
        d1 += __shfl_down_sync(0xffffffffu, d1, off);
        d2 += __shfl_down_sync(0xffffffffu, d2, off);
    }
    if (f4 == 0) {
        g_pre[node] = d1 + b_fc2[0];
        g_xc3[node] = d2;
    }
}

// ---------------- Final aggregate conv3 + output ----------------
__global__ __launch_bounds__(256) void agg3_kernel(
    const float* __restrict__ b_conv3, float* __restrict__ out, int n)
{
    int gw = (blockIdx.x * blockDim.x + threadIdx.x) >> 5;
    int lane = threadIdx.x & 31;
    if (gw >= n) return;
    int s = g_colptr[gw], e = g_colptr[gw + 1];
    float acc = 0.f;
    for (int p = s + lane; p < e; p += 32)
        acc += g_ewt[p] * g_xc3[g_erow[p]];
    #pragma unroll
    for (int off = 16; off > 0; off >>= 1)
        acc += __shfl_down_sync(0xffffffffu, acc, off);
    if (lane == 0)
        out[gw] = g_pre[gw] + b_conv3[0] + g_dis[gw] * acc;
}

// ---------------- launch ----------------
extern "C" void kernel_launch(void* const* d_in, const int* in_sizes, int n_in,
                              void* d_out, int out_size)
{
    const float* x        = (const float*)d_in[0];
    const void*  edges    = d_in[1];
    const float* w_fc     = (const float*)d_in[2];
    const float* b_fc     = (const float*)d_in[3];
    const float* w_conv1  = (const float*)d_in[4];
    const float* b_conv1  = (const float*)d_in[5];
    const float* w_fc1    = (const float*)d_in[6];
    const float* b_fc1    = (const float*)d_in[7];
    const float* w_conv2  = (const float*)d_in[8];
    const float* b_conv2  = (const float*)d_in[9];
    const float* w_fc2    = (const float*)d_in[10];
    const float* b_fc2    = (const float*)d_in[11];
    const float* w_conv3  = (const float*)d_in[12];
    const float* b_conv3  = (const float*)d_in[13];
    float* out = (float*)d_out;

    int n = in_sizes[0] / INDIM;   // 50000
    int E = in_sizes[1] / 2;       // 800000
    int NB = (n + SCB - 1) / SCB;

    // lazily created side stream + events (host-side only; first call is the
    // uncaptured correctness run, so creation never happens during capture).
    static cudaStream_t s2 = nullptr;
    static cudaEvent_t evRoot = nullptr, evX = nullptr, evW = nullptr, ev2 = nullptr;
    static bool attrs_set = false;
    if (!s2) {
        cudaStreamCreateWithFlags(&s2, cudaStreamNonBlocking);
        cudaEventCreateWithFlags(&evRoot, cudaEventDisableTiming);
        cudaEventCreateWithFlags(&evX, cudaEventDisableTiming);
        cudaEventCreateWithFlags(&evW, cudaEventDisableTiming);
        cudaEventCreateWithFlags(&ev2, cudaEventDisableTiming);
    }
    if (!attrs_set) {
        cudaFuncSetAttribute(gemm1_mma, cudaFuncAttributeMaxDynamicSharedMemorySize, G1_SMEM);
        cudaFuncSetAttribute(gemm2_mma, cudaFuncAttributeMaxDynamicSharedMemorySize, G2_SMEM);
        attrs_set = true;
    }

    int mtiles = (n + 127) / 128;

    // fork side stream off the capture-origin (legacy) stream
    cudaEventRecord(evRoot, 0);
    cudaStreamWaitEvent(s2, evRoot, 0);

    // ---- side stream: input/weight conversions + fc half of gemm1 ----
    conv_x_kernel<<<(n * INDIM + 255) / 256, 256, 0, s2>>>(x, n * INDIM);
    cudaEventRecord(evX, s2);                       // x16 ready (needed by aggx)
    conv_w1_kernel<<<(C2 * INDIM) / 256, 256, 0, s2>>>(w_fc, w_conv1);
    cudaEventRecord(evW, s2);                       // w1 split ready (needed by gemm1b)
    conv_w2_kernel<<<(256 * C2) / 256, 256, 0, s2>>>(w_fc1, w_conv2);
    dim3 g1a(mtiles, 2);
    gemm1_mma<<<g1a, 256, G1_SMEM, s2>>>(b_fc, b_conv1, 0, n);   // x1 half
    cudaEventRecord(ev2, s2);

    // ---- main stream: CSR build + aggx + conv half of gemm1 ----
    detect_kernel<<<1, 256>>>((const int*)edges, 4096);
    zero_deg_kernel<<<(n + 255) / 256, 256>>>(n);
    count_kernel<<<(E + 255) / 256, 256>>>(edges, E);
    scan_blocks_kernel<<<NB, SCB>>>(n);
    scan_sums_kernel<<<1, 1024>>>(NB);
    scan_add_kernel<<<NB, SCB>>>(n, E);
    fill_kernel<<<(E + 255) / 256, 256>>>(edges, E);

    cudaStreamWaitEvent(0, evX, 0);                 // x16 ready
    aggx_kernel<<<(n + 7) / 8, 128>>>(n);

    cudaStreamWaitEvent(0, evW, 0);
    dim3 g1b(mtiles, 2);
    gemm1_mma<<<g1b, 256, G1_SMEM>>>(b_fc, b_conv1, 2, n);       // x2 half

    cudaStreamWaitEvent(0, ev2, 0);                 // join: x3 + w2 ready
    gemm2_mma<<<mtiles, 512, G2_SMEM>>>(b_fc1, n);
    agg2_head_kernel<<<(n + 3) / 4, 128>>>(b_conv2, w_fc2, b_fc2, w_conv3, n);

    int blocks = (n * 32 + 255) / 256;
    agg3_kernel<<<blocks, 256>>>(b_conv3, out, n);
}

// round 17
// speedup vs baseline: 1.4730x; 1.4730x over previous
#include <cuda_runtime.h>
#include <cuda_fp16.h>
#include <cstdint>

// Problem constants (fixed by the dataset)
#define NN    50000
#define EE    800000
#define INDIM 64
#define HID   256
#define OUTD  128
#define C2    512   // 2*HID

// ---------------- device scratch (static: no allocation allowed) ----------------
__device__ __half g_x16 [NN * INDIM];   // x (fp16)
__device__ __half g_xa16[NN * INDIM];   // A_norm x (fp16)
__device__ __half g_x3f [NN * C2];      // x3 (fp16)
__device__ __half g_b1h[C2 * INDIM];    // B1[n][k] = concat(w_fc,w_conv1)^T fp16
__device__ __half g_b2h[256 * C2];      // B2[n][k] = concat(w_fc1,w_conv2)^T fp16
__device__ __half g_xc2[NN * OUTD];  // x3 @ w_conv2 (raw, fp16 — gather-bandwidth critical)
__device__ float g_x7 [NN * OUTD];   // x5 (fc1 branch)
__device__ float g_xc3[NN];
__device__ float g_pre[NN];
__device__ float g_dis[NN];
__device__ int   g_deg[NN];
__device__ int   g_colptr[NN + 1];
__device__ int   g_cursor[NN];
__device__ int   g_erow[EE];
__device__ float g_ewt [EE];
__device__ int   g_bsum[1024];
__device__ int   g_is64;

// ---------------- mma.sync helpers (sm_80-era PTX: valid on plain sm_103) ----------------
__device__ __forceinline__ uint32_t smem_u32(const void* p) {
    uint32_t a;
    asm("{ .reg .u64 t; cvta.to.shared.u64 t, %1; cvt.u32.u64 %0, t; }" : "=r"(a) : "l"(p));
    return a;
}
__device__ __forceinline__ void ldsm4(uint32_t* d, uint32_t addr) {
    asm volatile("ldmatrix.sync.aligned.m8n8.x4.shared.b16 {%0,%1,%2,%3}, [%4];"
                 : "=r"(d[0]), "=r"(d[1]), "=r"(d[2]), "=r"(d[3]) : "r"(addr));
}
__device__ __forceinline__ void mma_f16(float* c, const uint32_t* a, uint32_t b0, uint32_t b1) {
    asm volatile(
        "mma.sync.aligned.m16n8k16.row.col.f32.f16.f16.f32 "
        "{%0,%1,%2,%3}, {%4,%5,%6,%7}, {%8,%9}, {%0,%1,%2,%3};"
        : "+f"(c[0]), "+f"(c[1]), "+f"(c[2]), "+f"(c[3])
        : "r"(a[0]), "r"(a[1]), "r"(a[2]), "r"(a[3]), "r"(b0), "r"(b1));
}
// cp.async 16B with zero-fill predicate (src-size 0 -> zeros)
__device__ __forceinline__ void cpa(uint32_t dst, const void* src, int pred) {
    asm volatile("cp.async.cg.shared.global [%0], [%1], 16, %2;"
                 :: "r"(dst), "l"(src), "r"(pred ? 16 : 0) : "memory");
}
#define CP_COMMIT() asm volatile("cp.async.commit_group;" ::: "memory")
#define CP_WAIT(N)  asm volatile("cp.async.wait_group %0;" :: "n"(N) : "memory")

// SMEM layouts; stride 72 elems (144B rows, conflict-free ldmatrix)
#define LDS    72
#define TILEB  (128 * LDS * 2)     // 18432 bytes (128 rows x 64 fp16)

// GEMM1: A 128x64 + B 128x64
#define G_A    0
#define G_BH   TILEB
#define G1_SMEM (2 * TILEB)        // 36864

// GEMM2 (N-merged, hi-only B): A 128x64 + B 256x64 per stage
#define G2S_A   0
#define G2S_BH  TILEB              // 18432
#define G2_STAGE (3 * TILEB)       // 55296
#define G2_SMEM (2 * G2_STAGE)     // 110592 (double buffered)

// gemm1 chunk: MF=4, NF=4, single-product fp16: 6 LDSM feed 16 MMA per k-step.
__device__ __forceinline__ void chunk64_g1(uint32_t base, uint32_t offA, uint32_t offB,
                                           float acc[4][4][4]) {
    #pragma unroll
    for (int ks = 0; ks < 4; ks++) {
        uint32_t ka = ks * 32;                      // k16 step = 16 fp16 = 32 bytes
        uint32_t a[4][4], bh[4][2];
        #pragma unroll
        for (int mi = 0; mi < 4; mi++) ldsm4(a[mi], base + G_A + offA + mi * 2304 + ka);
        #pragma unroll
        for (int nj = 0; nj < 2; nj++) {
            uint32_t t[4];
            ldsm4(t, base + G_BH + offB + nj * 2304 + ka);
            bh[nj * 2][0] = t[0]; bh[nj * 2][1] = t[1];
            bh[nj * 2 + 1][0] = t[2]; bh[nj * 2 + 1][1] = t[3];
        }
        #pragma unroll
        for (int mi = 0; mi < 4; mi++)
            #pragma unroll
            for (int nf = 0; nf < 4; nf++)
                mma_f16(acc[mi][nf], a[mi], bh[nf][0], bh[nf][1]);
    }
}

// gemm2 chunk: MF=2, NF=8, single-product fp16: 6 LDSM feed 16 MMA per k-step.
__device__ __forceinline__ void chunk64_g2(uint32_t base, uint32_t offA, uint32_t offB,
                                           float acc[2][8][4]) {
    #pragma unroll
    for (int ks = 0; ks < 4; ks++) {
        uint32_t ka = ks * 32;
        uint32_t a[2][4], bh[8][2];
        #pragma unroll
        for (int mi = 0; mi < 2; mi++) ldsm4(a[mi], base + G2S_A + offA + mi * 2304 + ka);
        #pragma unroll
        for (int nj = 0; nj < 4; nj++) {
            uint32_t t[4];
            ldsm4(t, base + G2S_BH + offB + nj * 2304 + ka);
            bh[nj * 2][0] = t[0]; bh[nj * 2][1] = t[1];
            bh[nj * 2 + 1][0] = t[2]; bh[nj * 2 + 1][1] = t[3];
        }
        #pragma unroll
        for (int mi = 0; mi < 2; mi++)
            #pragma unroll
            for (int nf = 0; nf < 8; nf++)
                mma_f16(acc[mi][nf], a[mi], bh[nf][0], bh[nf][1]);
    }
}

// ---------------- edge dtype handling ----------------
__global__ void detect_kernel(const int* __restrict__ p, int nwords) {
    __shared__ int any;
    if (threadIdx.x == 0) any = 0;
    __syncthreads();
    int v = 0;
    for (int i = threadIdx.x; i < nwords; i += blockDim.x)
        if (i & 1) v |= p[i];
    if (v) atomicOr(&any, 1);
    __syncthreads();
    if (threadIdx.x == 0) g_is64 = (any == 0) ? 1 : 0;
}
__device__ __forceinline__ int edge_val(const void* e, long idx) {
    if (g_is64) return (int)((const long long*)e)[idx];
    return ((const int*)e)[idx];
}

// ---------------- CSR build ----------------
__global__ void zero_deg_kernel(int n) {
    int i = blockIdx.x * blockDim.x + threadIdx.x;
    if (i < n) g_deg[i] = 0;
}
__global__ void count_kernel(const void* __restrict__ edges, int E) {
    int e = blockIdx.x * blockDim.x + threadIdx.x;
    if (e < E) atomicAdd(&g_deg[edge_val(edges, (long)E + e)], 1);
}
#define SCB 512
__global__ void scan_blocks_kernel(int n) {
    __shared__ int sm[SCB];
    int i = blockIdx.x * SCB + threadIdx.x;
    int v = (i < n) ? g_deg[i] : 0;
    sm[threadIdx.x] = v;
    __syncthreads();
    for (int off = 1; off < SCB; off <<= 1) {
        int t = 0;
        if ((int)threadIdx.x >= off) t = sm[threadIdx.x - off];
        __syncthreads();
        sm[threadIdx.x] += t;
        __syncthreads();
    }
    if (i < n) g_colptr[i] = sm[threadIdx.x] - v;
    if (threadIdx.x == SCB - 1) g_bsum[blockIdx.x] = sm[SCB - 1];
}
__global__ void scan_sums_kernel(int nb) {
    __shared__ int sm[1024];
    int v = (threadIdx.x < (unsigned)nb) ? g_bsum[threadIdx.x] : 0;
    sm[threadIdx.x] = v;
    __syncthreads();
    for (int off = 1; off < 1024; off <<= 1) {
        int t = 0;
        if ((int)threadIdx.x >= off) t = sm[threadIdx.x - off];
        __syncthreads();
        sm[threadIdx.x] += t;
        __syncthreads();
    }
    if (threadIdx.x < (unsigned)nb) g_bsum[threadIdx.x] = sm[threadIdx.x] - v;
}
__global__ void scan_add_kernel(int n, int Etot) {
    int i = blockIdx.x * SCB + threadIdx.x;
    if (i < n) {
        int v = g_colptr[i] + g_bsum[blockIdx.x];
        g_colptr[i] = v;
        g_cursor[i] = v;
        int d = g_deg[i];
        g_dis[i] = (d > 0) ? rsqrtf((float)d) : 0.0f;
    }
    if (i == 0) g_colptr[n] = Etot;
}
__global__ void fill_kernel(const void* __restrict__ edges, int E) {
    int e = blockIdx.x * blockDim.x + threadIdx.x;
    if (e < E) {
        int r = edge_val(edges, e);
        int c = edge_val(edges, (long)E + e);
        int pos = atomicAdd(&g_cursor[c], 1);
        g_erow[pos] = r;
        g_ewt[pos]  = g_dis[r];
    }
}

// ---------------- conversions ----------------
__global__ void conv_x_kernel(const float* __restrict__ x, int total) {
    int i = blockIdx.x * blockDim.x + threadIdx.x;
    if (i < total) g_x16[i] = __float2half(x[i]);
}
// B1[n][k] = (n<256 ? w_fc[k][n] : w_conv1[k][n-256]),  [512 x 64], fp16
__global__ void conv_w1_kernel(const float* __restrict__ w_fc, const float* __restrict__ w_conv1) {
    int i = blockIdx.x * blockDim.x + threadIdx.x;   // 512*64
    int nidx = i >> 6, k = i & 63;
    float v = (nidx < 256) ? w_fc[k * 256 + nidx] : w_conv1[k * 256 + (nidx - 256)];
    g_b1h[i] = __float2half(v);
}
// B2[n][k] = (n<128 ? w_fc1[k][n] : w_conv2[k][n-128]),  [256 x 512], fp16
__global__ void conv_w2_kernel(const float* __restrict__ w_fc1, const float* __restrict__ w_conv2) {
    int i = blockIdx.x * blockDim.x + threadIdx.x;   // 256*512
    int nidx = i >> 9, k = i & 511;
    float v = (nidx < 128) ? w_fc1[k * 128 + nidx] : w_conv2[k * 128 + (nidx - 128)];
    g_b2h[i] = __float2half(v);
}

// ---------------- Aggregate X (propagate-then-transform for conv1) ----------------
// Gathers from fp16 x (half the traffic), accumulates fp32, 2-way unrolled.
__global__ __launch_bounds__(128) void aggx_kernel(int n) {
    int node = blockIdx.x * 8 + (threadIdx.x >> 4);
    int f4 = threadIdx.x & 15;
    if (node >= n) return;
    int s = g_colptr[node], e = g_colptr[node + 1];
    float4 acc = make_float4(0.f, 0.f, 0.f, 0.f);
    float4 acc2 = make_float4(0.f, 0.f, 0.f, 0.f);
    int p = s;
    for (; p + 2 <= e; p += 2) {
        int r0 = g_erow[p], r1 = g_erow[p + 1];
        float w0 = g_ewt[p], w1 = g_ewt[p + 1];
        uint2 u0 = ((const uint2*)g_x16)[(long)r0 * 16 + f4];
        uint2 u1 = ((const uint2*)g_x16)[(long)r1 * 16 + f4];
        float2 a0 = __half22float2(*(__half2*)&u0.x), b0 = __half22float2(*(__half2*)&u0.y);
        float2 a1 = __half22float2(*(__half2*)&u1.x), b1 = __half22float2(*(__half2*)&u1.y);
        acc.x += w0 * a0.x; acc.y += w0 * a0.y; acc.z += w0 * b0.x; acc.w += w0 * b0.y;
        acc2.x += w1 * a1.x; acc2.y += w1 * a1.y; acc2.z += w1 * b1.x; acc2.w += w1 * b1.y;
    }
    if (p < e) {
        int r0 = g_erow[p];
        float w0 = g_ewt[p];
        uint2 u0 = ((const uint2*)g_x16)[(long)r0 * 16 + f4];
        float2 a0 = __half22float2(*(__half2*)&u0.x), b0 = __half22float2(*(__half2*)&u0.y);
        acc.x += w0 * a0.x; acc.y += w0 * a0.y; acc.z += w0 * b0.x; acc.w += w0 * b0.y;
    }
    acc.x += acc2.x; acc.y += acc2.y; acc.z += acc2.z; acc.w += acc2.w;
    float di = g_dis[node];
    __half2 h01, h23;
    h01.x = __float2half(acc.x * di); h01.y = __float2half(acc.y * di);
    h23.x = __float2half(acc.z * di); h23.y = __float2half(acc.w * di);
    long base = (long)node * 64 + f4 * 4;
    *(__half2*)(g_xa16 + base)     = h01;
    *(__half2*)(g_xa16 + base + 2) = h23;
}

// ================= GEMM1 (HMMA fp16, single product): [N,64] @ [64,512] -> x3 fp16 ========
// ybase+y in {0,1}: A = x16,  bias b_fc     -> x1 (cols 0..255)
// ybase+y in {2,3}: A = xa16, bias b_conv1  -> x2 (cols 256..511)
__global__ __launch_bounds__(256) void gemm1_mma(const float* __restrict__ b_fc,
                                                 const float* __restrict__ b_conv1,
                                                 int ybase, int n) {
    extern __shared__ char smem[];
    uint32_t sb = smem_u32(smem);
    int tid = threadIdx.x, wid = tid >> 5, lane = tid & 31;
    int bm0 = blockIdx.x * 128, bn0 = (blockIdx.y + ybase) * 128;
    bool isfc = bn0 < 256;
    const __half* A = isfc ? g_x16 : g_xa16;
    int wm = (wid >> 2) * 64, wn = (wid & 3) * 32;

    #pragma unroll
    for (int i = 0; i < 4; i++) {
        int t = tid + i * 256;
        int row = t >> 3, j = t & 7;
        long grow = bm0 + row;
        uint4 va = make_uint4(0u, 0u, 0u, 0u);
        if (grow < n) va = ((const uint4*)(A + grow * 64))[j];
        *(uint4*)(smem + G_A + row * 144 + j * 16) = va;
        long rb = bn0 + row;
        *(uint4*)(smem + G_BH + row * 144 + j * 16) = ((const uint4*)(g_b1h + rb * 64))[j];
    }
    __syncthreads();

    int g = lane >> 3, r = lane & 7;
    uint32_t offA = (uint32_t)(((wm + (g & 1) * 8 + r) * LDS + (g >> 1) * 8) * 2);
    uint32_t offB = (uint32_t)(((wn + (g >> 1) * 8 + r) * LDS + (g & 1) * 8) * 2);

    float acc[4][4][4];
    #pragma unroll
    for (int mi = 0; mi < 4; mi++)
        #pragma unroll
        for (int nf = 0; nf < 4; nf++)
            #pragma unroll
            for (int q = 0; q < 4; q++) acc[mi][nf][q] = 0.f;

    chunk64_g1(sb, offA, offB, acc);

    int qrow = lane >> 2, qcol = (lane & 3) * 2;
    #pragma unroll
    for (int mi = 0; mi < 4; mi++) {
        int r0 = bm0 + wm + mi * 16 + qrow;
        int r1 = r0 + 8;
        #pragma unroll
        for (int nf = 0; nf < 4; nf++) {
            int col = bn0 + wn + nf * 8 + qcol;
            float* c = acc[mi][nf];
            float2 bb = isfc ? *(const float2*)(b_fc + col)
                             : *(const float2*)(b_conv1 + (col - 256));
            if (r0 < n) {
                __half2 o;
                o.x = __float2half(fmaxf(c[0] + bb.x, 0.f));
                o.y = __float2half(fmaxf(c[1] + bb.y, 0.f));
                *(__half2*)(g_x3f + (long)r0 * C2 + col) = o;
            }
            if (r1 < n) {
                __half2 o;
                o.x = __float2half(fmaxf(c[2] + bb.x, 0.f));
                o.y = __float2half(fmaxf(c[3] + bb.y, 0.f));
                *(__half2*)(g_x3f + (long)r1 * C2 + col) = o;
            }
        }
    }
}

// ================= GEMM2 (HMMA fp16, N-merged 128x256 tile, hi-only B, cp.async 2-stage) ====
// cols 0..127  -> relu(+b_fc1) -> g_x7 (x5, fp32)
// cols 128..255-> raw fp16     -> g_xc2
__global__ __launch_bounds__(512) void gemm2_mma(const float* __restrict__ b_fc1, int n) {
    extern __shared__ char smem[];
    uint32_t sb = smem_u32(smem);
    int tid = threadIdx.x, wid = tid >> 5, lane = tid & 31;
    int bm0 = blockIdx.x * 128;
    int wm = (wid & 3) * 32, wn = (wid >> 2) * 64;   // 16 warps: 4 m x 4 n of 32x64
    bool isfc = wn < 128;

    auto issue = [&](int c, int buf) {
        uint32_t base = sb + buf * G2_STAGE;
        int k0 = c * 64;
        // A: 1024 quads
        #pragma unroll
        for (int i = 0; i < 2; i++) {
            int t = tid + i * 512;
            int row = t >> 3, j = t & 7;
            long grow = bm0 + row;
            int pred = grow < n;
            cpa(base + G2S_A + row * 144 + j * 16,
                g_x3f + (pred ? grow : 0) * C2 + k0 + j * 8, pred);
        }
        // B hi: 2048 quads (rows 0..255 global)
        #pragma unroll
        for (int i = 0; i < 4; i++) {
            int t = tid + i * 512;
            int row = t >> 3, j = t & 7;
            cpa(base + G2S_BH + row * 144 + j * 16, g_b2h + (long)row * C2 + k0 + j * 8, 1);
        }
        CP_COMMIT();
    };

    int g = lane >> 3, r = lane & 7;
    uint32_t offA = (uint32_t)(((wm + (g & 1) * 8 + r) * LDS + (g >> 1) * 8) * 2);
    uint32_t offB = (uint32_t)(((wn + (g >> 1) * 8 + r) * LDS + (g & 1) * 8) * 2);

    float acc[2][8][4];
    #pragma unroll
    for (int mi = 0; mi < 2; mi++)
        #pragma unroll
        for (int nf = 0; nf < 8; nf++)
            #pragma unroll
            for (int q = 0; q < 4; q++) acc[mi][nf][q] = 0.f;

    issue(0, 0);
    for (int c = 0; c < 8; c++) {
        if (c < 7) {
            issue(c + 1, (c + 1) & 1);
            CP_WAIT(1);
        } else {
            CP_WAIT(0);
        }
        __syncthreads();
        chunk64_g2(sb + (c & 1) * G2_STAGE, offA, offB, acc);
        __syncthreads();
    }

    int qrow = lane >> 2, qcol = (lane & 3) * 2;
    #pragma unroll
    for (int mi = 0; mi < 2; mi++) {
        int r0 = bm0 + wm + mi * 16 + qrow;
        int r1 = r0 + 8;
        #pragma unroll
        for (int nf = 0; nf < 8; nf++) {
            int col = wn + nf * 8 + qcol;     // 0..255
            float* c = acc[mi][nf];
            if (isfc) {
                float2 bb = *(const float2*)(b_fc1 + col);
                if (r0 < n) {
                    float2 o = make_float2(fmaxf(c[0] + bb.x, 0.f), fmaxf(c[1] + bb.y, 0.f));
                    *(float2*)(g_x7 + (long)r0 * OUTD + col) = o;
                }
                if (r1 < n) {
                    float2 o = make_float2(fmaxf(c[2] + bb.x, 0.f), fmaxf(c[3] + bb.y, 0.f));
                    *(float2*)(g_x7 + (long)r1 * OUTD + col) = o;
                }
            } else {
                int cc = col - 128;
                if (r0 < n) {
                    __half2 o; o.x = __float2half(c[0]); o.y = __float2half(c[1]);
                    *(__half2*)(g_xc2 + (long)r0 * OUTD + cc) = o;
                }
                if (r1 < n) {
                    __half2 o; o.x = __float2half(c[2]); o.y = __float2half(c[3]);
                    *(__half2*)(g_xc2 + (long)r1 * OUTD + cc) = o;
                }
            }
        }
    }
}

// ---------- Fused aggregate conv2 + head (fp16 gather, 2-way unrolled) ----------
__global__ __launch_bounds__(128) void agg2_head_kernel(
    const float* __restrict__ b_conv2, const float* __restrict__ w_fc2,
    const float* __restrict__ b_fc2, const float* __restrict__ w_conv3, int n)
{
    int node = blockIdx.x * 4 + (threadIdx.x >> 5);
    int f4 = threadIdx.x & 31;
    if (node >= n) return;
    int s = g_colptr[node], e = g_colptr[node + 1];
    float4 acc = make_float4(0.f, 0.f, 0.f, 0.f);
    float4 acc2 = make_float4(0.f, 0.f, 0.f, 0.f);
    int p = s;
    for (; p + 2 <= e; p += 2) {
        int r0 = g_erow[p], r1 = g_erow[p + 1];
        float w0 = g_ewt[p], w1 = g_ewt[p + 1];
        uint2 u0 = ((const uint2*)g_xc2)[(long)r0 * 32 + f4];
        uint2 u1 = ((const uint2*)g_xc2)[(long)r1 * 32 + f4];
        float2 a0 = __half22float2(*(__half2*)&u0.x), b0 = __half22float2(*(__half2*)&u0.y);
        float2 a1 = __half22float2(*(__half2*)&u1.x), b1 = __half22float2(*(__half2*)&u1.y);
        acc.x += w0 * a0.x; acc.y += w0 * a0.y; acc.z += w0 * b0.x; acc.w += w0 * b0.y;
        acc2.x += w1 * a1.x; acc2.y += w1 * a1.y; acc2.z += w1 * b1.x; acc2.w += w1 * b1.y;
    }
    if (p < e) {
        int r0 = g_erow[p];
        float w0 = g_ewt[p];
        uint2 u0 = ((const uint2*)g_xc2)[(long)r0 * 32 + f4];
        float2 a0 = __half22float2(*(__half2*)&u0.x), b0 = __half22float2(*(__half2*)&u0.y);
        acc.x += w0 * a0.x; acc.y += w0 * a0.y; acc.z += w0 * b0.x; acc.w += w0 * b0.y;
    }
    acc.x += acc2.x; acc.y += acc2.y; acc.z += acc2.z; acc.w += acc2.w;
    float di = g_dis[node];
    float4 b = ((const float4*)b_conv2)[f4];
    float4 cur = ((const float4*)g_x7)[(long)node * 32 + f4];   // x5
    cur.x += fmaxf(acc.x * di + b.x, 0.f);
    cur.y += fmaxf(acc.y * di + b.y, 0.f);
    cur.z += fmaxf(acc.z * di + b.z, 0.f);
    cur.w += fmaxf(acc.w * di + b.w, 0.f);
    // head dots (x7 never stored)
    float4 wf = ((const float4*)w_fc2)[f4];
    float4 wc = ((const float4*)w_conv3)[f4];
    float d1 = cur.x * wf.x + cur.y * wf.y + cur.z * wf.z + cur.w * wf.w;
    float d2 = cur.x * wc.x + cur.y * wc.y + cur.z * wc.z + cur.w * wc.w;
    #pragma unroll
    for (int off = 16; off > 0; off >>= 1) {
        d1 += __shfl_down_sync(0xffffffffu, d1, off);
        d2 += __shfl_down_sync(0xffffffffu, d2, off);
    }
    if (f4 == 0) {
        g_pre[node] = d1 + b_fc2[0];
        g_xc3[node] = d2;
    }
}

// ---------------- Final aggregate conv3 + output ----------------
__global__ __launch_bounds__(256) void agg3_kernel(
    const float* __restrict__ b_conv3, float* __restrict__ out, int n)
{
    int gw = (blockIdx.x * blockDim.x + threadIdx.x) >> 5;
    int lane = threadIdx.x & 31;
    if (gw >= n) return;
    int s = g_colptr[gw], e = g_colptr[gw + 1];
    float acc = 0.f;
    for (int p = s + lane; p < e; p += 32)
        acc += g_ewt[p] * g_xc3[g_erow[p]];
    #pragma unroll
    for (int off = 16; off > 0; off >>= 1)
        acc += __shfl_down_sync(0xffffffffu, acc, off);
    if (lane == 0)
        out[gw] = g_pre[gw] + b_conv3[0] + g_dis[gw] * acc;
}

// ---------------- launch ----------------
extern "C" void kernel_launch(void* const* d_in, const int* in_sizes, int n_in,
                              void* d_out, int out_size)
{
    const float* x        = (const float*)d_in[0];
    const void*  edges    = d_in[1];
    const float* w_fc     = (const float*)d_in[2];
    const float* b_fc     = (const float*)d_in[3];
    const float* w_conv1  = (const float*)d_in[4];
    const float* b_conv1  = (const float*)d_in[5];
    const float* w_fc1    = (const float*)d_in[6];
    const float* b_fc1    = (const float*)d_in[7];
    const float* w_conv2  = (const float*)d_in[8];
    const float* b_conv2  = (const float*)d_in[9];
    const float* w_fc2    = (const float*)d_in[10];
    const float* b_fc2    = (const float*)d_in[11];
    const float* w_conv3  = (const float*)d_in[12];
    const float* b_conv3  = (const float*)d_in[13];
    float* out = (float*)d_out;

    int n = in_sizes[0] / INDIM;   // 50000
    int E = in_sizes[1] / 2;       // 800000
    int NB = (n + SCB - 1) / SCB;

    // lazily created side stream + events (host-side only; first call is the
    // uncaptured correctness run, so creation never happens during capture).
    static cudaStream_t s2 = nullptr;
    static cudaEvent_t evRoot = nullptr, evX = nullptr, evW = nullptr, ev2 = nullptr;
    static bool attrs_set = false;
    if (!s2) {
        cudaStreamCreateWithFlags(&s2, cudaStreamNonBlocking);
        cudaEventCreateWithFlags(&evRoot, cudaEventDisableTiming);
        cudaEventCreateWithFlags(&evX, cudaEventDisableTiming);
        cudaEventCreateWithFlags(&evW, cudaEventDisableTiming);
        cudaEventCreateWithFlags(&ev2, cudaEventDisableTiming);
    }
    if (!attrs_set) {
        cudaFuncSetAttribute(gemm1_mma, cudaFuncAttributeMaxDynamicSharedMemorySize, G1_SMEM);
        cudaFuncSetAttribute(gemm2_mma, cudaFuncAttributeMaxDynamicSharedMemorySize, G2_SMEM);
        attrs_set = true;
    }

    int mtiles = (n + 127) / 128;

    // fork side stream off the capture-origin (legacy) stream
    cudaEventRecord(evRoot, 0);
    cudaStreamWaitEvent(s2, evRoot, 0);

    // ---- side stream: input/weight conversions + fc half of gemm1 ----
    conv_x_kernel<<<(n * INDIM + 255) / 256, 256, 0, s2>>>(x, n * INDIM);
    cudaEventRecord(evX, s2);                       // x16 ready (needed by aggx)
    conv_w1_kernel<<<(C2 * INDIM) / 256, 256, 0, s2>>>(w_fc, w_conv1);
    cudaEventRecord(evW, s2);                       // w1 ready (needed by gemm1b)
    conv_w2_kernel<<<(256 * C2) / 256, 256, 0, s2>>>(w_fc1, w_conv2);
    dim3 g1a(mtiles, 2);
    gemm1_mma<<<g1a, 256, G1_SMEM, s2>>>(b_fc, b_conv1, 0, n);   // x1 half
    cudaEventRecord(ev2, s2);

    // ---- main stream: CSR build + aggx + conv half of gemm1 ----
    detect_kernel<<<1, 256>>>((const int*)edges, 4096);
    zero_deg_kernel<<<(n + 255) / 256, 256>>>(n);
    count_kernel<<<(E + 255) / 256, 256>>>(edges, E);
    scan_blocks_kernel<<<NB, SCB>>>(n);
    scan_sums_kernel<<<1, 1024>>>(NB);
    scan_add_kernel<<<NB, SCB>>>(n, E);
    fill_kernel<<<(E + 255) / 256, 256>>>(edges, E);

    cudaStreamWaitEvent(0, evX, 0);                 // x16 ready
    aggx_kernel<<<(n + 7) / 8, 128>>>(n);

    cudaStreamWaitEvent(0, evW, 0);
    dim3 g1b(mtiles, 2);
    gemm1_mma<<<g1b, 256, G1_SMEM>>>(b_fc, b_conv1, 2, n);       // x2 half

    cudaStreamWaitEvent(0, ev2, 0);                 // join: x3 + w2 ready
    gemm2_mma<<<mtiles, 512, G2_SMEM>>>(b_fc1, n);
    agg2_head_kernel<<<(n + 3) / 4, 128>>>(b_conv2, w_fc2, b_fc2, w_conv3, n);

    int blocks = (n * 32 + 255) / 256;
    agg3_kernel<<<blocks, 256>>>(b_conv3, out, n);
}